// round 1
// baseline (speedup 1.0000x reference)
#include <cuda_runtime.h>
#include <float.h>
#include <math.h>

#define NI 128
#define NC 256
#define RR 36
#define WW 48
#define DD 256

#define IMG_STR 260      // img row stride (floats), mult of 4 for float4, bank-friendly
#define CAPT_STR 49      // capT row stride (floats), odd -> conflict-free w-scans
#define A_STR 37         // A row stride
#define PART_STR 49
#define NT 192

// shared memory layout (float offsets)
#define OFF_IMG  0
#define OFF_CAPT (OFF_IMG + RR*IMG_STR)          // 9360
#define OFF_SP   (OFF_CAPT + DD*CAPT_STR)        // 21904  Spart[2][36][48]
#define OFF_SP1  (OFF_SP + RR*WW)                // 23632
#define OFF_A    (OFF_SP + 2*RR*WW)              // 25360  A[48][37]
#define OFF_W1   (OFF_A + WW*A_STR)              // 27136
#define OFF_RINV (OFF_W1 + WW)                   // 27184
#define OFF_RS   (OFF_RINV + RR)                 // 27220
#define SMEM_FLOATS (OFF_RS + WW)                // 27268 -> 109072 bytes
// partial-reduction buffers alias Spart[1] (dead after phase 3a)
#define OFF_P12  OFF_SP1
#define OFF_PSQ  (OFF_SP1 + 16*PART_STR)         // 784+784 <= 1728 ok

extern __shared__ float sm[];

__global__ void __launch_bounds__(NT, 2)
scan_kernel(const float* __restrict__ images,
            const float* __restrict__ captions,
            float* __restrict__ out)
{
    const int c = blockIdx.x;   // caption
    const int i = blockIdx.y;   // image
    const int t = threadIdx.x;

    float* img  = sm + OFF_IMG;    // [36][260]
    float* capT = sm + OFF_CAPT;   // [256][49]  (d-major, w contiguous)
    float* Sp   = sm + OFF_SP;     // [2][36][48] k-split partials, then combined S in Sp[0]
    float* A    = sm + OFF_A;      // [48][37] softmax weights (w-major)
    float* w1a  = sm + OFF_W1;     // [48]  |caption word|
    float* rinv = sm + OFF_RINV;   // [36]  1/(||S row||+eps)
    float* rs   = sm + OFF_RS;     // [48]  row_sim * LAMBDA_LSE
    float* p12  = sm + OFF_P12;    // [16][49]
    float* psq  = sm + OFF_PSQ;    // [16][49]

    // ---------------- Phase 1: load tiles ----------------
    {
        const float4* gi = (const float4*)(images + (size_t)i * RR * DD);
        for (int idx = t; idx < RR * DD / 4; idx += NT) {
            float4 v = gi[idx];
            int r = idx >> 6;            // 64 float4 per 256-row
            int d = (idx & 63) << 2;
            *(float4*)(img + r * IMG_STR + d) = v;
        }
        const float4* gc = (const float4*)(captions + (size_t)c * WW * DD);
        for (int idx = t; idx < WW * DD / 4; idx += NT) {
            float4 v = gc[idx];
            int w = idx >> 6;
            int d = (idx & 63) << 2;
            capT[(d + 0) * CAPT_STR + w] = v.x;
            capT[(d + 1) * CAPT_STR + w] = v.y;
            capT[(d + 2) * CAPT_STR + w] = v.z;
            capT[(d + 3) * CAPT_STR + w] = v.w;
        }
    }
    __syncthreads();

    // ---------------- Phase 2: S[r][w] = sum_d img[r][d]*cap[w][d] ----------------
    // 192 thr = 2 k-slices x (12 r-groups x 8 w-groups); per-thread tile 3r x 6w
    {
        int ks = t / 96;
        int t2 = t % 96;
        int rg = t2 >> 3;          // 0..11
        int wg = t2 & 7;           // 0..7
        int r0 = rg * 3, w0 = wg * 6;

        float acc[3][6];
        #pragma unroll
        for (int jr = 0; jr < 3; jr++)
            #pragma unroll
            for (int jw = 0; jw < 6; jw++) acc[jr][jw] = 0.f;

        const int dbeg = ks * 128;
        const float* ip0 = img + r0 * IMG_STR;
        #pragma unroll 2
        for (int d = dbeg; d < dbeg + 128; ++d) {
            float iv[3], cv[6];
            #pragma unroll
            for (int jr = 0; jr < 3; jr++) iv[jr] = ip0[jr * IMG_STR + d];
            const float* cp = capT + d * CAPT_STR + w0;
            #pragma unroll
            for (int jw = 0; jw < 6; jw++) cv[jw] = cp[jw];
            #pragma unroll
            for (int jr = 0; jr < 3; jr++)
                #pragma unroll
                for (int jw = 0; jw < 6; jw++)
                    acc[jr][jw] = fmaf(iv[jr], cv[jw], acc[jr][jw]);
        }
        float* sp = Sp + ks * (RR * WW);
        #pragma unroll
        for (int jr = 0; jr < 3; jr++)
            #pragma unroll
            for (int jw = 0; jw < 6; jw++)
                sp[(r0 + jr) * WW + (w0 + jw)] = acc[jr][jw];
    }
    __syncthreads();

    // ---------------- Phase 3a: combine k-slices, leaky_relu, row l2norm; |cap_w| ----------------
    if (t < RR) {
        int r = t;
        float ss = 0.f;
        for (int w = 0; w < WW; ++w) {
            float v = Sp[r * WW + w] + Sp[RR * WW + r * WW + w];
            v = (v >= 0.f) ? v : 0.1f * v;       // leaky_relu slope 0.1
            Sp[r * WW + w] = v;
            ss = fmaf(v, v, ss);
        }
        rinv[r] = 1.f / (sqrtf(ss) + 1e-8f);
    } else if (t >= 64 && t < 64 + WW) {
        int w = t - 64;
        float ss = 0.f;
        for (int d = 0; d < DD; ++d) {
            float v = capT[d * CAPT_STR + w];
            ss = fmaf(v, v, ss);
        }
        w1a[w] = sqrtf(ss);
    }
    __syncthreads();

    // ---------------- Phase 3b: softmax over r (per w), lambda=9 -> A[w][r] ----------------
    if (t < WW) {
        int w = t;
        float m = -FLT_MAX;
        for (int r = 0; r < RR; ++r) {
            float v = 9.f * Sp[r * WW + w] * rinv[r];
            m = fmaxf(m, v);
        }
        float s = 0.f;
        for (int r = 0; r < RR; ++r) {
            float v = 9.f * Sp[r * WW + w] * rinv[r];
            float e = __expf(v - m);
            A[w * A_STR + r] = e;
            s += e;
        }
        float is = 1.f / s;
        for (int r = 0; r < RR; ++r) A[w * A_STR + r] *= is;
    }
    __syncthreads();

    // ---------------- Phase 4+5: wctx = A @ img, fused cosine partials ----------------
    // 192 thr = 12 w-groups x 16 d-groups; per-thread 4w x 8d, 2 chunks over d
    {
        int wg = t >> 4;          // 0..11
        int dg = t & 15;          // 0..15
        int w0 = wg * 4;

        float pp12[4] = {0.f, 0.f, 0.f, 0.f};
        float ppsq[4] = {0.f, 0.f, 0.f, 0.f};

        #pragma unroll
        for (int chunk = 0; chunk < 2; ++chunk) {
            int d0 = chunk * 128 + dg * 8;
            float acc[4][8];
            #pragma unroll
            for (int j = 0; j < 4; j++)
                #pragma unroll
                for (int dd = 0; dd < 8; dd++) acc[j][dd] = 0.f;

            for (int k = 0; k < RR; ++k) {
                float a0 = A[(w0 + 0) * A_STR + k];
                float a1 = A[(w0 + 1) * A_STR + k];
                float a2 = A[(w0 + 2) * A_STR + k];
                float a3 = A[(w0 + 3) * A_STR + k];
                float4 v0 = *(const float4*)(img + k * IMG_STR + d0);
                float4 v1 = *(const float4*)(img + k * IMG_STR + d0 + 4);
                float iv[8] = {v0.x, v0.y, v0.z, v0.w, v1.x, v1.y, v1.z, v1.w};
                #pragma unroll
                for (int dd = 0; dd < 8; dd++) {
                    acc[0][dd] = fmaf(a0, iv[dd], acc[0][dd]);
                    acc[1][dd] = fmaf(a1, iv[dd], acc[1][dd]);
                    acc[2][dd] = fmaf(a2, iv[dd], acc[2][dd]);
                    acc[3][dd] = fmaf(a3, iv[dd], acc[3][dd]);
                }
            }
            // cosine partials for this d-slice
            #pragma unroll
            for (int j = 0; j < 4; j++) {
                #pragma unroll
                for (int dd = 0; dd < 8; dd++) {
                    float cv = capT[(d0 + dd) * CAPT_STR + (w0 + j)];
                    pp12[j] = fmaf(acc[j][dd], cv, pp12[j]);
                    ppsq[j] = fmaf(acc[j][dd], acc[j][dd], ppsq[j]);
                }
            }
        }
        #pragma unroll
        for (int j = 0; j < 4; j++) {
            p12[dg * PART_STR + w0 + j] = pp12[j];
            psq[dg * PART_STR + w0 + j] = ppsq[j];
        }
    }
    __syncthreads();

    // ---------------- Phase 6: cosine + LogSumExp ----------------
    if (t < WW) {
        int w = t;
        float s12 = 0.f, ssq = 0.f;
        #pragma unroll
        for (int g = 0; g < 16; ++g) {
            s12 += p12[g * PART_STR + w];
            ssq += psq[g * PART_STR + w];
        }
        float w2 = sqrtf(ssq);
        float denom = fmaxf(w1a[w] * w2, 1e-8f);
        rs[w] = (s12 / denom) * 6.f;   // row_sim * LAMBDA_LSE
    }
    __syncthreads();

    if (t < 32) {
        float v0 = rs[t];
        float v1 = (t < 16) ? rs[32 + t] : -FLT_MAX;
        float m = fmaxf(v0, v1);
        #pragma unroll
        for (int off = 16; off; off >>= 1)
            m = fmaxf(m, __shfl_xor_sync(0xffffffffu, m, off));
        float s = __expf(v0 - m) + ((t < 16) ? __expf(v1 - m) : 0.f);
        #pragma unroll
        for (int off = 16; off; off >>= 1)
            s += __shfl_xor_sync(0xffffffffu, s, off);
        if (t == 0)
            out[(size_t)i * NC + c] = (m + logf(s)) * (1.f / 6.f);
    }
}

extern "C" void kernel_launch(void* const* d_in, const int* in_sizes, int n_in,
                              void* d_out, int out_size)
{
    const float* images   = (const float*)d_in[0];   // (128, 36, 256) fp32
    const float* captions = (const float*)d_in[1];   // (256, 48, 256) fp32
    float* out = (float*)d_out;                       // (128, 256) fp32

    cudaFuncSetAttribute(scan_kernel,
                         cudaFuncAttributeMaxDynamicSharedMemorySize,
                         SMEM_FLOATS * (int)sizeof(float));

    dim3 grid(NC, NI);
    scan_kernel<<<grid, NT, SMEM_FLOATS * sizeof(float)>>>(images, captions, out);
}